// round 5
// baseline (speedup 1.0000x reference)
#include <cuda_runtime.h>
#include <math.h>

// Bicubic clamped B-spline surface evaluation (NUM_CP=64, degree 3, weights=1).
// Inputs (metadata order): eu [N], ev [N], control_points [64*64*3].
// Output: surface_points [N,4] then normals [N,4], concatenated floats.

#define NCP 64
#define NSPANS 61           // interior spans: knots[3..64] = linspace(0,1,62)

// Control points repacked as float4 (x,y,z,unused) — 64 KB, L1/L2 resident.
__device__ float4 g_cp4[NCP * NCP];

__global__ void prep_cp_kernel(const float* __restrict__ cp) {
    int i = blockIdx.x * blockDim.x + threadIdx.x;
    if (i < NCP * NCP) {
        g_cp4[i] = make_float4(cp[3 * i + 0], cp[3 * i + 1], cp[3 * i + 2], 0.0f);
    }
}

// Span per reference _find_span: searchsorted(right)-1 clipped to [3,63],
// snapped to 63 when u is within tol of knots[63] = 60/61.
__device__ __forceinline__ int spanf(float u) {
    int s = 3 + (int)(u * (float)NSPANS);   // u > 0 -> trunc == floor
    s = max(3, min(s, NCP - 1));
    const float kn = 60.0f / 61.0f;
    if (fabsf(u - kn) <= 1e-5f + 1e-5f * kn) s = NCP - 1;
    return s;
}

// Reciprocal of a knot-difference denominator d/61, d in {1,2,3} (as float).
// Pure ALU: two selects, no MUFU.
__device__ __forceinline__ float inv_d(float d) {
    return (d < 1.5f) ? 61.0f : ((d < 2.5f) ? 30.5f : (61.0f / 3.0f));
}

// Cubic basis values N0[0..3] and first derivatives N1[0..3] at u for given span.
// Cox-de Boor, degree 3, nth=1 closed form. All denominators are knot
// differences (u-independent), reduced to exact reciprocals of d/61.
__device__ __forceinline__ void basis3(float u, int span, float* N0, float* N1) {
    const float s61 = 1.0f / 61.0f;
    float fs  = (float)span;
    // clamped knot integers (as floats): knots[span+k] = clamp(span+k-3,0,61)/61
    float c0  = fminf(fs, 61.0f);          // span     (span<=63 -> upper clamp only)
    float cm1 = fminf(fs - 1.0f, 61.0f);   // span-1
    float cm2 = fs - 2.0f;                 // span-2 in [1,61], no clamp
    float cm3 = fs - 3.0f;                 // span-3 in [0,60], no clamp
    float cm4 = fmaxf(fs - 4.0f, 0.0f);    // span-4
    float cm5 = fmaxf(fs - 5.0f, 0.0f);    // span-5

    float left1  = fmaf(cm3, -s61, u);     // u - knots[span]
    float left2  = fmaf(cm4, -s61, u);     // u - knots[span-1]
    float left3  = fmaf(cm5, -s61, u);     // u - knots[span-2]
    float right1 = fmaf(cm2,  s61, -u);    // knots[span+1] - u
    float right2 = fmaf(cm1,  s61, -u);    // knots[span+2] - u
    float right3 = fmaf(c0,   s61, -u);    // knots[span+3] - u

    // denominator reciprocals (exact; d = integer knot-index difference)
    float i10 = inv_d(cm2 - cm3);
    float i20 = inv_d(cm2 - cm4);
    float i21 = inv_d(cm1 - cm3);
    float i30 = inv_d(cm2 - cm5);
    float i31 = inv_d(cm1 - cm4);
    float i32 = inv_d(c0  - cm3);

    // j = 1
    float n01 = right1 * i10;              // ndu[0][1]
    float n11 = left1  * i10;              // ndu[1][1]

    // j = 2
    float t    = n01 * i20;
    float n02  = right1 * t;               // ndu[0][2]
    float saved = left2 * t;
    t          = n11 * i21;
    float n12  = fmaf(right2, t, saved);   // ndu[1][2]
    float n22  = left1 * t;                // ndu[2][2]

    // j = 3 (quotients q_r reused for the derivative closed form)
    float q0 = n02 * i30;
    N0[0] = right1 * q0;
    saved = left3 * q0;
    float q1 = n12 * i31;
    N0[1] = fmaf(right2, q1, saved);
    saved = left2 * q1;
    float q2 = n22 * i32;
    N0[2] = fmaf(right3, q2, saved);
    N0[3] = left1 * q2;

    // nth=1 derivative: N1[r] = 3 * (q_{r-1} - q_r)
    N1[0] = -3.0f * q0;
    N1[1] =  3.0f * (q0 - q1);
    N1[2] =  3.0f * (q1 - q2);
    N1[3] =  3.0f * q2;
}

__global__ void __launch_bounds__(256)
nurbs_eval_kernel(const float* __restrict__ eu, const float* __restrict__ ev,
                  float4* __restrict__ out_sp, float4* __restrict__ out_nr, int n) {
    int idx = blockIdx.x * blockDim.x + threadIdx.x;
    if (idx >= n) return;

    float u = eu[idx];
    float v = ev[idx];
    int se = spanf(u);
    int sn = spanf(v);

    float be0[4], be1[4], bn0[4], bn1[4];
    basis3(u, se, be0, be1);
    basis3(v, sn, bn0, bn1);

    float Sx = 0.f, Sy = 0.f, Sz = 0.f;       // surface point
    float Ux = 0.f, Uy = 0.f, Uz = 0.f;       // d/du
    float Vx = 0.f, Vy = 0.f, Vz = 0.f;       // d/dv

    int base = (se - 3) * NCP + (sn - 3);
#pragma unroll
    for (int r = 0; r < 4; r++) {
        const float4* row = &g_cp4[base + r * NCP];
        float t0x = 0.f, t0y = 0.f, t0z = 0.f;
        float t1x = 0.f, t1y = 0.f, t1z = 0.f;
#pragma unroll
        for (int s = 0; s < 4; s++) {
            float4 P = __ldg(&row[s]);
            t0x = fmaf(bn0[s], P.x, t0x);
            t0y = fmaf(bn0[s], P.y, t0y);
            t0z = fmaf(bn0[s], P.z, t0z);
            t1x = fmaf(bn1[s], P.x, t1x);
            t1y = fmaf(bn1[s], P.y, t1y);
            t1z = fmaf(bn1[s], P.z, t1z);
        }
        Sx = fmaf(be0[r], t0x, Sx);
        Sy = fmaf(be0[r], t0y, Sy);
        Sz = fmaf(be0[r], t0z, Sz);
        Ux = fmaf(be1[r], t0x, Ux);
        Uy = fmaf(be1[r], t0y, Uy);
        Uz = fmaf(be1[r], t0z, Uz);
        Vx = fmaf(be0[r], t1x, Vx);
        Vy = fmaf(be0[r], t1y, Vy);
        Vz = fmaf(be0[r], t1z, Vz);
    }

    // normal = normalize(cross(du, dv)); denom = max(|n|, 1e-12)
    float nx = Uy * Vz - Uz * Vy;
    float ny = Uz * Vx - Ux * Vz;
    float nz = Ux * Vy - Uy * Vx;
    float d = nx * nx + ny * ny + nz * nz;
    float inv = rsqrtf(fmaxf(d, 1e-24f));   // == 1/max(norm,1e-12) for d<=1e-24 too

    out_sp[idx] = make_float4(Sx, Sy, Sz, 1.0f);   // weight channel: partition of unity
    out_nr[idx] = make_float4(nx * inv, ny * inv, nz * inv, 0.0f);
}

extern "C" void kernel_launch(void* const* d_in, const int* in_sizes, int n_in,
                              void* d_out, int out_size) {
    const float* eu = (const float*)d_in[0];
    const float* ev = (const float*)d_in[1];
    const float* cp = (const float*)d_in[2];
    int n = in_sizes[0];

    prep_cp_kernel<<<(NCP * NCP + 255) / 256, 256>>>(cp);

    float* out = (float*)d_out;
    float4* out_sp = (float4*)out;
    float4* out_nr = (float4*)(out + (size_t)n * 4);
    nurbs_eval_kernel<<<(n + 255) / 256, 256>>>(eu, ev, out_sp, out_nr, n);
}